// round 1
// baseline (speedup 1.0000x reference)
#include <cuda_runtime.h>
#include <cuda_bf16.h>

// out[h] = sum_n ne_nodes[n, h]
//
// The reference's attention weights are softmax over axis=1 of an [N,1]
// tensor -> identically 1.0, so the entire MLP path (this_node, relations,
// W1, b1, W2, b2) is dead code. The kernel is a pure 200000x256 fp32
// column reduction: ~205 MB HBM read, DRAM-bound.

#define HIDDEN 256
#define NPART  512   // number of partial-sum blocks in pass 1

// Scratch for deterministic two-pass reduction (no device allocs allowed).
// Laid out transposed: g_partial[col * NPART + block] so pass 2 is coalesced.
__device__ float g_partial[HIDDEN * NPART];

// Pass 1: each block b strides rows {b, b+NPART, ...}; thread tid owns
// column tid. Every loop iteration the block reads one contiguous 1KB row
// (fully coalesced). Unroll x4 -> ptxas front-batches 4 independent LDGs
// per thread (high MLP) to saturate HBM.
__global__ __launch_bounds__(HIDDEN) void colsum_partial(
    const float* __restrict__ ne, int n_rows)
{
    const int tid = threadIdx.x;   // column index 0..255
    const int b   = blockIdx.x;    // partial index 0..NPART-1

    float acc = 0.0f;
    int r = b;
    // main unrolled loop: 4 independent loads in flight per thread
    for (; r + 3 * NPART < n_rows; r += 4 * NPART) {
        float a0 = ne[(r             ) * HIDDEN + tid];
        float a1 = ne[(r +     NPART ) * HIDDEN + tid];
        float a2 = ne[(r + 2 * NPART ) * HIDDEN + tid];
        float a3 = ne[(r + 3 * NPART ) * HIDDEN + tid];
        acc += (a0 + a1) + (a2 + a3);
    }
    for (; r < n_rows; r += NPART) {
        acc += ne[r * HIDDEN + tid];
    }

    g_partial[tid * NPART + b] = acc;
}

// Pass 2: one block per column; 256 threads each fold 2 of the 512 partials,
// then warp-shuffle + shared tree reduce. Fixed reduction order ->
// deterministic output. Traffic ~2MB (L2-resident), negligible time.
__global__ __launch_bounds__(256) void colsum_final(float* __restrict__ out)
{
    const int col = blockIdx.x;    // 0..255
    const int t   = threadIdx.x;   // 0..255

    float s = g_partial[col * NPART + t] + g_partial[col * NPART + t + 256];

    // warp reduce
    #pragma unroll
    for (int o = 16; o > 0; o >>= 1)
        s += __shfl_down_sync(0xffffffffu, s, o);

    __shared__ float ws[8];
    if ((t & 31) == 0) ws[t >> 5] = s;
    __syncthreads();

    if (t < 8) {
        s = ws[t];
        #pragma unroll
        for (int o = 4; o > 0; o >>= 1)
            s += __shfl_down_sync(0xffu, s, o);
        if (t == 0) out[col] = s;
    }
}

extern "C" void kernel_launch(void* const* d_in, const int* in_sizes, int n_in,
                              void* d_out, int out_size)
{
    // metadata order: this_node[0], relations[1], ne_nodes[2], W1[3], b1[4], W2[5], b2[6]
    const float* ne = (const float*)d_in[2];
    const int n_rows = in_sizes[2] / HIDDEN;   // 200000
    float* out = (float*)d_out;                // 256 floats

    colsum_partial<<<NPART, HIDDEN>>>(ne, n_rows);
    colsum_final<<<HIDDEN, 256>>>(out);
}

// round 2
// speedup vs baseline: 1.1070x; 1.1070x over previous
#include <cuda_runtime.h>
#include <cuda_bf16.h>

// out[h] = sum_n ne_nodes[n, h]
//
// The reference's attention weights are softmax over axis=1 of an [N,1]
// tensor -> identically 1.0, so the entire MLP path is dead code. The real
// workload is a 200000x256 fp32 column reduction: ~205 MB HBM read,
// DRAM-bound. Two-pass deterministic reduction, fully float4-vectorized.

#define HIDDEN 256
#define QUADS  (HIDDEN / 4)   // 64 float4 column-quads per row
#define NPART  512            // pass-1 grid (partials per column-quad)
#define T1     256            // pass-1 block size

// Scratch (no device allocs allowed). Transposed layout:
// g_partial4[quad * NPART + block] -> pass 2 is coalesced.
__device__ float4 g_partial4[QUADS * NPART];

static __device__ __forceinline__ float4 f4add(float4 a, float4 b) {
    float4 r;
    r.x = a.x + b.x; r.y = a.y + b.y; r.z = a.z + b.z; r.w = a.w + b.w;
    return r;
}

// Pass 1: grid-stride over the tensor viewed as float4[n_rows*64].
// stride = NPART*T1 = 131072 (multiple of 64), so each thread's
// column-quad (index % 64) is fixed = tid % 64. Unroll x4 -> 4 independent
// LDG.128 in flight per thread (64 B/thread, ~8 MB chip-wide) to saturate
// HBM. Within a block, the 4 threads sharing a quad combine via smem.
__global__ __launch_bounds__(T1) void colsum_partial(
    const float4* __restrict__ ne4, int total4)
{
    const int tid = threadIdx.x;
    const int gid = blockIdx.x * T1 + tid;
    const int stride = NPART * T1;            // 131072

    float4 acc = make_float4(0.f, 0.f, 0.f, 0.f);
    int f = gid;
    for (; f + 3 * stride < total4; f += 4 * stride) {
        float4 a = ne4[f];
        float4 b = ne4[f + stride];
        float4 c = ne4[f + 2 * stride];
        float4 d = ne4[f + 3 * stride];
        acc = f4add(acc, f4add(f4add(a, b), f4add(c, d)));
    }
    for (; f < total4; f += stride)
        acc = f4add(acc, ne4[f]);

    __shared__ float4 sm[T1];
    sm[tid] = acc;
    __syncthreads();

    if (tid < QUADS) {
        // threads tid, tid+64, tid+128, tid+192 all own quad `tid`
        float4 r = f4add(f4add(sm[tid],        sm[tid + 64]),
                         f4add(sm[tid + 128],  sm[tid + 192]));
        g_partial4[tid * NPART + blockIdx.x] = r;
    }
}

// Pass 2: one block per column-quad; 128 threads each fold 4 of the 512
// partials (coalesced LDG.128), then warp-shuffle + smem tree reduce.
// Fixed reduction order -> deterministic. ~512 KB L2-resident traffic.
__global__ __launch_bounds__(128) void colsum_final(float* __restrict__ out)
{
    const int cq = blockIdx.x;     // 0..63
    const int t  = threadIdx.x;    // 0..127

    const float4* p = g_partial4 + cq * NPART;
    float4 s = f4add(f4add(p[t],        p[t + 128]),
                     f4add(p[t + 256],  p[t + 384]));

    #pragma unroll
    for (int o = 16; o > 0; o >>= 1) {
        s.x += __shfl_down_sync(0xffffffffu, s.x, o);
        s.y += __shfl_down_sync(0xffffffffu, s.y, o);
        s.z += __shfl_down_sync(0xffffffffu, s.z, o);
        s.w += __shfl_down_sync(0xffffffffu, s.w, o);
    }

    __shared__ float4 ws[4];
    if ((t & 31) == 0) ws[t >> 5] = s;
    __syncthreads();

    if (t == 0) {
        float4 r = f4add(f4add(ws[0], ws[1]), f4add(ws[2], ws[3]));
        reinterpret_cast<float4*>(out)[cq] = r;
    }
}

extern "C" void kernel_launch(void* const* d_in, const int* in_sizes, int n_in,
                              void* d_out, int out_size)
{
    // metadata order: this_node[0], relations[1], ne_nodes[2], W1[3], b1[4], W2[5], b2[6]
    const float4* ne4 = (const float4*)d_in[2];
    const int total4 = in_sizes[2] / 4;        // 200000*256/4 = 12,800,000
    float* out = (float*)d_out;                // 256 floats

    colsum_partial<<<NPART, T1>>>(ne4, total4);
    colsum_final<<<QUADS, 128>>>(out);
}

// round 4
// speedup vs baseline: 1.1088x; 1.0017x over previous
#include <cuda_runtime.h>
#include <cuda_bf16.h>

// out[h] = sum_n ne_nodes[n, h]
//
// The reference's attention weights are softmax over axis=1 of an [N,1]
// tensor -> identically 1.0, so the entire MLP path is dead code. True
// workload: 200000x256 fp32 column reduction, ~205 MB HBM read, DRAM-bound.
//
// Single fused kernel (R2 showed a second launch costs a fixed ~4.4us):
// all blocks stream partials, then the first 64 blocks spin on a monotonic
// arrival counter (graph-replay safe, no reset needed) and each finishes
// one float4 column-quad. Fixed reduction order -> deterministic.

#define HIDDEN 256
#define QUADS  (HIDDEN / 4)     // 64 float4 column-quads per row
#define NPART  592              // 148 SMs * 4 CTAs -> perfectly balanced wave
#define T1     256

__device__ float4   g_partial4[QUADS * NPART];
__device__ unsigned g_ctr;      // monotonic arrival counter (never reset)

static __device__ __forceinline__ float4 f4add(float4 a, float4 b) {
    float4 r;
    r.x = a.x + b.x; r.y = a.y + b.y; r.z = a.z + b.z; r.w = a.w + b.w;
    return r;
}

__global__ __launch_bounds__(T1) void colsum_fused(
    const float4* __restrict__ ne4, int total4, float* __restrict__ out)
{
    const int tid = threadIdx.x;
    const int bid = blockIdx.x;
    const int gid = bid * T1 + tid;
    const int stride = NPART * T1;          // 151552, multiple of 64
                                            // -> thread's quad fixed = tid & 63

    // ---- phase 1: stream 205 MB, 8 independent LDG.128 in flight ----
    float4 acc = make_float4(0.f, 0.f, 0.f, 0.f);
    int f = gid;
    for (; f + 7 * stride < total4; f += 8 * stride) {
        float4 a0 = ne4[f];
        float4 a1 = ne4[f +     stride];
        float4 a2 = ne4[f + 2 * stride];
        float4 a3 = ne4[f + 3 * stride];
        float4 a4 = ne4[f + 4 * stride];
        float4 a5 = ne4[f + 5 * stride];
        float4 a6 = ne4[f + 6 * stride];
        float4 a7 = ne4[f + 7 * stride];
        float4 s0 = f4add(f4add(a0, a1), f4add(a2, a3));
        float4 s1 = f4add(f4add(a4, a5), f4add(a6, a7));
        acc = f4add(acc, f4add(s0, s1));
    }
    for (; f < total4; f += stride)
        acc = f4add(acc, ne4[f]);

    // ---- block-local combine: 4 threads share each quad ----
    __shared__ float4 sm[T1];
    sm[tid] = acc;
    __syncthreads();

    if (tid < QUADS) {
        float4 r = f4add(f4add(sm[tid],       sm[tid + 64]),
                         f4add(sm[tid + 128], sm[tid + 192]));
        g_partial4[tid * NPART + bid] = r;
    }
    __syncthreads();

    // ---- publish arrival (release), get this launch's epoch target ----
    __shared__ unsigned s_tgt;
    if (tid == 0) {
        __threadfence();                    // partials visible device-wide
        unsigned o = atomicAdd(&g_ctr, 1u);
        s_tgt = (o / NPART + 1u) * NPART;   // monotonic: no reset per replay
    }

    if (bid >= QUADS) return;               // only blocks 0..63 finish

    __syncthreads();
    if (tid == 0) {
        const unsigned target = s_tgt;
        unsigned cur;
        do {
            asm volatile("ld.acquire.gpu.u32 %0, [%1];"
                         : "=r"(cur) : "l"(&g_ctr) : "memory");
            if (cur >= target) break;
            __nanosleep(64);
        } while (true);
    }
    __syncthreads();                        // acquire propagates to block

    // ---- final reduce for quad `bid`: 592 partials, coalesced from L2 ----
    const float4* p = g_partial4 + bid * NPART;
    float4 s = make_float4(0.f, 0.f, 0.f, 0.f);
    for (int i = tid; i < NPART; i += T1)   // i = tid, tid+256 (tid<80)
        s = f4add(s, p[i]);

    #pragma unroll
    for (int o = 16; o > 0; o >>= 1) {
        s.x += __shfl_down_sync(0xffffffffu, s.x, o);
        s.y += __shfl_down_sync(0xffffffffu, s.y, o);
        s.z += __shfl_down_sync(0xffffffffu, s.z, o);
        s.w += __shfl_down_sync(0xffffffffu, s.w, o);
    }

    __shared__ float4 ws[T1 / 32];
    if ((tid & 31) == 0) ws[tid >> 5] = s;
    __syncthreads();

    if (tid == 0) {
        float4 r = ws[0];
        #pragma unroll
        for (int w = 1; w < T1 / 32; ++w) r = f4add(r, ws[w]);
        reinterpret_cast<float4*>(out)[bid] = r;
    }
}

extern "C" void kernel_launch(void* const* d_in, const int* in_sizes, int n_in,
                              void* d_out, int out_size)
{
    // metadata order: this_node[0], relations[1], ne_nodes[2], W1[3], b1[4], W2[5], b2[6]
    const float4* ne4 = (const float4*)d_in[2];
    const int total4 = in_sizes[2] / 4;        // 12,800,000
    float* out = (float*)d_out;                // 256 floats

    colsum_fused<<<NPART, T1>>>(ne4, total4, out);
}

// round 5
// speedup vs baseline: 1.1155x; 1.0060x over previous
#include <cuda_runtime.h>
#include <cuda_bf16.h>

// out[h] = sum_n ne_nodes[n, h]
//
// Reference's softmax is over axis=1 of an [N,1] tensor -> att == 1.0, the
// whole MLP path is dead code. True workload: 200000x256 fp32 column sum,
// ~205 MB HBM read, DRAM-bound (~33 us streaming floor at ~6.2 TB/s).
//
// Single fused kernel. R4 lesson: making blocks 0..63 the finishers made the
// FIRST arrivals wait out the FULL completion spread (~3.8us tail = the cost
// of the launch we deleted). Fix: elect the LAST 64 arrivals at the counter
// as finishers -- the last arriver waits for nobody, the 529th only for the
// 63 behind it. Output stays deterministic: partials are keyed by chunk id,
// final sum is in fixed chunk order, independent of which block computes it.

#define HIDDEN 256
#define QUADS  (HIDDEN / 4)     // 64 float4 column-quads
#define NPART  592              // 148 SMs * 4 CTAs, one balanced wave
#define T1     256

__device__ float4   g_partial4[QUADS * NPART];
__device__ unsigned g_ctr;      // monotonic arrival counter (never reset;
                                // graph replays are stream-serialized, so
                                // epoch = ctr / NPART)

static __device__ __forceinline__ float4 f4add(float4 a, float4 b) {
    float4 r;
    r.x = a.x + b.x; r.y = a.y + b.y; r.z = a.z + b.z; r.w = a.w + b.w;
    return r;
}

__global__ __launch_bounds__(T1) void colsum_fused(
    const float4* __restrict__ ne4, int total4, float* __restrict__ out)
{
    const int tid = threadIdx.x;
    const int bid = blockIdx.x;
    const int gid = bid * T1 + tid;
    const int stride = NPART * T1;          // 151552, multiple of 64
                                            // -> thread's quad fixed = tid & 63

    // ---- phase 1: stream 205 MB, 8 independent LDG.128 in flight ----
    float4 acc = make_float4(0.f, 0.f, 0.f, 0.f);
    int f = gid;
    for (; f + 7 * stride < total4; f += 8 * stride) {
        float4 a0 = ne4[f];
        float4 a1 = ne4[f +     stride];
        float4 a2 = ne4[f + 2 * stride];
        float4 a3 = ne4[f + 3 * stride];
        float4 a4 = ne4[f + 4 * stride];
        float4 a5 = ne4[f + 5 * stride];
        float4 a6 = ne4[f + 6 * stride];
        float4 a7 = ne4[f + 7 * stride];
        float4 s0 = f4add(f4add(a0, a1), f4add(a2, a3));
        float4 s1 = f4add(f4add(a4, a5), f4add(a6, a7));
        acc = f4add(acc, f4add(s0, s1));
    }
    for (; f < total4; f += stride)
        acc = f4add(acc, ne4[f]);

    // ---- block-local combine: 4 threads share each quad ----
    __shared__ float4 sm[T1];
    sm[tid] = acc;
    __syncthreads();

    if (tid < QUADS) {
        float4 r = f4add(f4add(sm[tid],       sm[tid + 64]),
                         f4add(sm[tid + 128], sm[tid + 192]));
        g_partial4[tid * NPART + bid] = r;
    }
    __syncthreads();

    // ---- publish arrival with RELEASE (no gpu-scope fence -> no L1 flush).
    //      __syncthreads above gives intra-block HB for the tid<64 stores;
    //      the release-atomic by tid 0 publishes them device-wide. ----
    __shared__ unsigned s_pos, s_tgt;
    if (tid == 0) {
        unsigned o;
        asm volatile("atom.add.release.gpu.u32 %0, [%1], %2;"
                     : "=r"(o) : "l"(&g_ctr), "r"(1u) : "memory");
        s_pos = o % NPART;                       // arrival rank in this epoch
        s_tgt = (o / NPART + 1u) * NPART;        // epoch completion target
    }
    __syncthreads();

    const unsigned pos = s_pos;
    if (pos < NPART - QUADS) return;             // early arrivals: done

    // ---- this block is one of the last 64 arrivals: finish one quad ----
    const int quad = (NPART - 1) - (int)pos;     // last arriver -> quad 0

    if (tid == 0) {
        const unsigned target = s_tgt;
        unsigned cur;
        do {
            asm volatile("ld.acquire.gpu.u32 %0, [%1];"
                         : "=r"(cur) : "l"(&g_ctr) : "memory");
            if (cur >= target) break;
            __nanosleep(32);
        } while (true);
    }
    __syncthreads();                             // acquire propagates to block

    // ---- final reduce for `quad`: 592 partials, coalesced from L2 ----
    const float4* p = g_partial4 + quad * NPART;
    float4 s = make_float4(0.f, 0.f, 0.f, 0.f);
    for (int i = tid; i < NPART; i += T1)        // fixed order -> deterministic
        s = f4add(s, p[i]);

    #pragma unroll
    for (int o = 16; o > 0; o >>= 1) {
        s.x += __shfl_down_sync(0xffffffffu, s.x, o);
        s.y += __shfl_down_sync(0xffffffffu, s.y, o);
        s.z += __shfl_down_sync(0xffffffffu, s.z, o);
        s.w += __shfl_down_sync(0xffffffffu, s.w, o);
    }

    __shared__ float4 ws[T1 / 32];
    if ((tid & 31) == 0) ws[tid >> 5] = s;
    __syncthreads();

    if (tid == 0) {
        float4 r = ws[0];
        #pragma unroll
        for (int w = 1; w < T1 / 32; ++w) r = f4add(r, ws[w]);
        reinterpret_cast<float4*>(out)[quad] = r;
    }
}

extern "C" void kernel_launch(void* const* d_in, const int* in_sizes, int n_in,
                              void* d_out, int out_size)
{
    // metadata order: this_node[0], relations[1], ne_nodes[2], W1[3], b1[4], W2[5], b2[6]
    const float4* ne4 = (const float4*)d_in[2];
    const int total4 = in_sizes[2] / 4;        // 12,800,000
    float* out = (float*)d_out;                // 256 floats

    colsum_fused<<<NPART, T1>>>(ne4, total4, out);
}